// round 2
// baseline (speedup 1.0000x reference)
#include <cuda_runtime.h>
#include <math.h>

// ---------------------------------------------------------------------------
// Problem constants: x is (8,3,1024,1024) fp32. 16x16 DCT blocks.
// 24 images of 1024x1024 -> 64x64 blocks each -> 98304 blocks total.
// CTA handles a horizontal strip of 16 blocks (16 rows x 256 cols).
// Grid = 98304/16 = 6144 CTAs, 256 threads each.
// ---------------------------------------------------------------------------

#define NB 16            // DCT blocks per CTA
#define ROWSTRIDE 17     // smem row stride (floats) - bank-conflict-free
#define BLKSTRIDE 272    // smem per-block stride (16*17) -> +16 banks between halves
#define N_BLOCKS_TOTAL 98304
#define GRID_DIM 6144

// Compile-time cos via constexpr Taylor (folds DCT coeffs into FFMA immediates)
constexpr double PI_D = 3.14159265358979323846;
__host__ __device__ constexpr double ccos(double x) {
    while (x > PI_D)  x -= 2.0 * PI_D;
    while (x < -PI_D) x += 2.0 * PI_D;
    double x2 = x * x;
    double term = 1.0, sum = 1.0;
    for (int i = 1; i <= 16; ++i) {
        term *= -x2 / double((2 * i - 1) * (2 * i));
        sum += term;
    }
    return sum;
}
__host__ __device__ constexpr float CN(int n) {  // cos(n*pi/32)
    return (float)ccos(n * PI_D / 32.0);
}

// Zigzag upper-band table (indices into flattened 16x16 coeff block)
static __device__ const unsigned char g_zz[128] = {
    135, 150, 165, 180, 195, 210, 225, 240, 241, 226, 211, 196, 181, 166, 151,
    136, 121, 106, 91, 76, 61, 46, 31, 47, 62, 77, 92, 107, 122, 137, 152, 167,
    182, 197, 212, 227, 242, 243, 228, 213, 198, 183, 168, 153, 138, 123, 108,
    93, 78, 63, 79, 94, 109, 124, 139, 154, 169, 184, 199, 214, 229, 244, 245,
    230, 215, 200, 185, 170, 155, 140, 125, 110, 95, 111, 126, 141, 156, 171,
    186, 201, 216, 231, 246, 247, 232, 217, 202, 187, 172, 157, 142, 127, 143,
    158, 173, 188, 203, 218, 233, 248, 249, 234, 219, 204, 189, 174, 159, 175,
    190, 205, 220, 235, 250, 251, 236, 221, 206, 191, 207, 222, 237, 252, 253,
    238, 223, 239, 254, 255};

__device__ double g_acc = 0.0;

// 16-point DCT-II (unnormalized): o[i] = sum_k x[k] * cos((2k+1)*i*pi/32)
// 3-level even/odd butterfly decomposition: ~115 ops instead of 256.
__device__ __forceinline__ void dct16(const float x[16], float o[16]) {
    float s[8], d[8];
#pragma unroll
    for (int k = 0; k < 8; ++k) { s[k] = x[k] + x[15 - k]; d[k] = x[k] - x[15 - k]; }
    // odd outputs: full 8-tap on d
#pragma unroll
    for (int i = 1; i < 16; i += 2) {
        float acc = d[0] * CN(i);
#pragma unroll
        for (int k = 1; k < 8; ++k) acc = fmaf(d[k], CN((2 * k + 1) * i), acc);
        o[i] = acc;
    }
    // even outputs: 8-pt DCT of s
    float s2[4], d2[4];
#pragma unroll
    for (int k = 0; k < 4; ++k) { s2[k] = s[k] + s[7 - k]; d2[k] = s[k] - s[7 - k]; }
#pragma unroll
    for (int m = 1; m < 8; m += 2) {
        float acc = d2[0] * CN(2 * m);
#pragma unroll
        for (int k = 1; k < 4; ++k) acc = fmaf(d2[k], CN(2 * (2 * k + 1) * m), acc);
        o[2 * m] = acc;
    }
    // 4-pt DCT of s2
    float s3_0 = s2[0] + s2[3], s3_1 = s2[1] + s2[2];
    float d3_0 = s2[0] - s2[3], d3_1 = s2[1] - s2[2];
    o[4]  = fmaf(d3_1, CN(12), d3_0 * CN(4));
    o[12] = fmaf(d3_1, CN(36), d3_0 * CN(12));
    o[0]  = s3_0 + s3_1;
    o[8]  = (s3_0 - s3_1) * CN(8);
}

__global__ __launch_bounds__(256) void ube_kernel(const float* __restrict__ in) {
    __shared__ float sw[NB * BLKSTRIDE];
    __shared__ float spart[NB];

    const int tid = threadIdx.x;
    const int blk = tid >> 4;   // DCT block within CTA (0..15)
    const int col = tid & 15;   // column within DCT block

    // strip decode: 256 strips per (b,c) image; 4 strips per 16-row block-row
    const int s    = blockIdx.x;
    const int img  = s >> 8;
    const int rem  = s & 255;
    const int brow = rem >> 2;
    const int scol = rem & 3;
    const float* p = in + (size_t)img * (1024u * 1024u) + brow * (16 * 1024) +
                     scol * 256 + tid;

    // ---- load one column (coalesced 128B per warp per row) ----
    float x[16];
#pragma unroll
    for (int r = 0; r < 16; ++r) x[r] = p[r * 1024];

    // ---- stage 1: column DCT (vertical). Only rows 1..15 are ever gathered. ----
    float o[16];
    dct16(x, o);
    float* wbuf = sw + blk * BLKSTRIDE;
#pragma unroll
    for (int i = 1; i < 16; ++i) wbuf[(i - 1) * ROWSTRIDE + col] = o[i];
    __syncwarp();

    // ---- stage 2: row DCT. Threads 1..15 handle rows 1..15. ----
    if (col != 0) {
        float wr[16];
        const int base = (col - 1) * ROWSTRIDE;
#pragma unroll
        for (int k = 0; k < 16; ++k) wr[k] = wbuf[base + k];
        float cf[16];
        dct16(wr, cf);
#pragma unroll
        for (int j = 0; j < 16; ++j) wbuf[base + j] = cf[j];
    }
    __syncwarp();

    // ---- zigzag gather with folded normalization ----
    // coeff = SCALE * n_r * n_c * dct;  gathered rows have r>=1 so n_r = 1.
    // n_c = 1/sqrt(2) only for c==0 (zigzag index 240). SCALE = 1/sqrt(32).
    float v[8];
#pragma unroll
    for (int u = 0; u < 8; ++u) {
        const int idx = g_zz[col * 8 + u];
        const int r = idx >> 4, c = idx & 15;
        const float sc = (c == 0) ? 0.125f : 0.17677669529663689f;
        v[u] = wbuf[(r - 1) * ROWSTRIDE + c] * sc;
    }

    // per-block mean over 128 (reduce across the 16-lane group: xor 8,4,2,1)
    float sum = ((v[0] + v[1]) + (v[2] + v[3])) + ((v[4] + v[5]) + (v[6] + v[7]));
#pragma unroll
    for (int m = 8; m >= 1; m >>= 1) sum += __shfl_xor_sync(0xffffffffu, sum, m);
    const float mean = sum * (1.0f / 128.0f);

    // threshold + partial entropy sums
    float sa = 0.0f, sq = 0.0f, sl = 0.0f;
#pragma unroll
    for (int u = 0; u < 8; ++u) {
        const float f = (v[u] < mean) ? 0.0f : v[u];
        const float a = fabsf(f) + 1e-12f;
        sa += a;
        sq  = fmaf(a, a, sq);
        sl  = fmaf(a, __log2f(a), sl);
    }
#pragma unroll
    for (int m = 8; m >= 1; m >>= 1) {
        sa += __shfl_xor_sync(0xffffffffu, sa, m);
        sq += __shfl_xor_sync(0xffffffffu, sq, m);
        sl += __shfl_xor_sync(0xffffffffu, sl, m);
    }

    // entropy = (log2(s)*sum(a) - sum(a*log2 a)) / s,  s = max(||a||2, 1e-12)
    if (col == 0) {
        const float nrm = fmaxf(sqrtf(sq), 1e-12f);
        spart[blk] = (__log2f(nrm) * sa - sl) / nrm;
    }
    __syncthreads();
    if (tid == 0) {
        float c0 = 0.0f;
#pragma unroll
        for (int b = 0; b < NB; ++b) c0 += spart[b];
        atomicAdd(&g_acc, (double)c0);
    }
}

__global__ void ube_finalize(float* __restrict__ out) {
    out[0] = (float)(g_acc * (1.0 / (double)N_BLOCKS_TOTAL));
    g_acc = 0.0;  // reset for the next (graph-replayed) invocation
}

extern "C" void kernel_launch(void* const* d_in, const int* in_sizes, int n_in,
                              void* d_out, int out_size) {
    const float* x = (const float*)d_in[0];
    float* out = (float*)d_out;
    ube_kernel<<<GRID_DIM, 256>>>(x);
    ube_finalize<<<1, 1>>>(out);
}